// round 10
// baseline (speedup 1.0000x reference)
#include <cuda_runtime.h>
#include <cstdint>

typedef unsigned long long ull;

#define SEQ 64
#define DM 32
#define DI 64
#define HW 1024
#define TT 8

#define FMA2(d, a, b, c) \
    asm("fma.rn.f32x2 %0, %1, %2, %3;" : "=l"(d) : "l"(a), "l"(b), "l"(c))
#define MUL2(d, a, b) \
    asm("mul.rn.f32x2 %0, %1, %2;" : "=l"(d) : "l"(a), "l"(b))
__device__ __forceinline__ ull pack2(float lo, float hi) {
    ull r; asm("mov.b64 %0, {%1, %2};" : "=l"(r) : "f"(lo), "f"(hi)); return r;
}
__device__ __forceinline__ float2 unpack2(ull v) {
    float2 f; asm("mov.b64 {%0, %1}, %2;" : "=f"(f.x), "=f"(f.y) : "l"(v)); return f;
}
__device__ __forceinline__ ull lds64v(uint32_t a) {
    ull v; asm volatile("ld.shared.b64 %0, [%1];" : "=l"(v) : "r"(a)); return v;
}
__device__ __forceinline__ float4 lds128v(uint32_t a) {
    float4 v;
    asm volatile("ld.shared.v4.f32 {%0,%1,%2,%3}, [%4];"
                 : "=f"(v.x), "=f"(v.y), "=f"(v.z), "=f"(v.w) : "r"(a));
    return v;
}

__device__ float g_xr[2 * HW * SEQ * DM];

__global__ __launch_bounds__(256) void transpose_kernel(const float* __restrict__ x) {
    __shared__ float tile[DM][65];
    const int bi = blockIdx.x;
    const int c  = bi & 15;
    const int t  = (bi >> 4) & 63;
    const int b  = bi >> 10;
    const float* src = x + ((b * SEQ + t) * DM) * HW + c * 64;
    const int tid = threadIdx.x;
    #pragma unroll
    for (int i = 0; i < 8; i++) {
        int idx = tid + i * 256;
        tile[idx >> 6][idx & 63] = src[(idx >> 6) * HW + (idx & 63)];
    }
    __syncthreads();
    #pragma unroll
    for (int i = 0; i < 8; i++) {
        int idx = tid + i * 256;
        int hw = idx >> 5, m = idx & 31;
        g_xr[(b * HW + c * 64 + hw) * (SEQ * DM) + t * DM + m] = tile[m][hw];
    }
}

// Block: 256 threads = 4 teams x 64 threads; each team handles 2 sequences.
__global__ __launch_bounds__(256, 2) void mamba_main(
    const float* __restrict__ in_proj_w, const float* __restrict__ conv_w,
    const float* __restrict__ conv_b, const float* __restrict__ x_proj_w,
    const float* __restrict__ dt_proj_w, const float* __restrict__ dt_proj_b,
    const float* __restrict__ A_log, const float* __restrict__ Dp,
    const float* __restrict__ out_proj_w, const float* __restrict__ lin1_w,
    const float* __restrict__ lin1_b, const float* __restrict__ lin2_w,
    const float* __restrict__ lin2_b, float* __restrict__ out)
{
    __shared__ float4 winp4[8][128];          // in_proj 4-wide; r<64 xh, r>=64 z
    __shared__ float4 xpw4[8][64];            // B/C half-row 4-wide, i = 32w + l
    __shared__ ull    wdt_u[64];              // dt rows 0/1 pairs
    __shared__ float  xin_s[2][4][2][TT][DM]; // [buf][team][seq][tt][m]
    __shared__ float  xt_s[4][2][TT][72];     // half0 @[0..31], half1 @[36..67]
    __shared__ float  sz_s[4][2][TT][DI];     // silu(z)
    __shared__ float  dbc_s[4][2][TT][40];    // [0:16)B,[16:32)C,[32]u0,[33]u1
    __shared__ float  part_s[4][2][SEQ][2];
    __shared__ float  wm_s[DM];
    __shared__ float  v_s[DI];
    __shared__ float  a_s[DI][18];
    __shared__ float  c_s;
    __shared__ int    slow_s;

    const int tid = threadIdx.x;
    const int team = tid >> 6;
    const int d = tid & 63;
    const int w = (tid >> 5) & 1;
    const int l = tid & 31;

    if (tid == 0) slow_s = 0;
    for (int idx = tid; idx < 1024; idx += 256) {
        int qq = idx >> 7, r = idx & 127;
        winp4[qq][r] = *(const float4*)&in_proj_w[r * DM + 4 * qq];
    }
    for (int idx = tid; idx < 512; idx += 256) {
        int qq = idx >> 6, i = idx & 63;
        int wi = i >> 5, li = i & 31;
        int row = 2 + 16 * wi + (li >> 1), half = li & 1;
        xpw4[qq][i] = *(const float4*)&x_proj_w[row * DI + 32 * half + 4 * qq];
    }
    if (tid < 64) {
        int wi = tid >> 5, li = tid & 31;
        float2 p = *(const float2*)&x_proj_w[wi * DI + 2 * li];
        wdt_u[tid] = pack2(p.x, p.y);
    }
    if (tid < DM) {
        float acc = 0.f;
        #pragma unroll
        for (int k = 0; k < 16; k++) acc = fmaf(lin2_w[k], lin1_w[k * 32 + tid], acc);
        wm_s[tid] = acc;
    }
    if (tid == 0) {
        float c = lin2_b[0];
        #pragma unroll
        for (int k = 0; k < 16; k++) c = fmaf(lin2_w[k], lin1_b[k], c);
        c_s = c;
    }
    __syncthreads();
    if (tid < DI) {
        float acc = 0.f;
        #pragma unroll
        for (int m = 0; m < 32; m++) acc = fmaf(wm_s[m], out_proj_w[m * 64 + tid], acc);
        v_s[tid] = acc;
        int bad = 0;
        #pragma unroll
        for (int n = 0; n < 16; n++) {
            float a = -__expf(A_log[tid * 16 + n]);
            a_s[tid][n] = a;
            if (fabsf(a + (float)(n + 1)) > 1e-4f * (float)(n + 1)) bad = 1;
        }
        if (bad) atomicOr(&slow_s, 1);
    }

    const float4 cw = *(const float4*)(conv_w + d * 4);
    const float cb = conv_b[d];
    const float2 dtw = *(const float2*)(dt_proj_w + d * 2);
    const float dtb = dt_proj_b[d];
    const float dpv = Dp[d];

    const int bb0 = blockIdx.x * 8 + team * 2;
    const float* xbase = g_xr + (size_t)bb0 * (SEQ * DM);
    // preload tile 0 for both seqs: 2 float4 per thread
    #pragma unroll
    for (int r = 0; r < 2; r++) {
        int f = d + 64 * r;           // 0..127
        int s = f >> 6, rem = f & 63;
        float4 v4 = *(const float4*)(xbase + s * (SEQ * DM) + rem * 4);
        *(float4*)&xin_s[0][team][s][rem >> 3][(rem & 7) * 4] = v4;
    }
    __syncthreads();
    const float vv = v_s[d];
    const int slow = slow_s;

    const uint32_t winp_a = (uint32_t)__cvta_generic_to_shared(&winp4[0][0]);
    const uint32_t xpw_a  = (uint32_t)__cvta_generic_to_shared(&xpw4[0][0]);
    const uint32_t wdt_a  = (uint32_t)__cvta_generic_to_shared(&wdt_u[0]);

    const int xpos = (d < 32) ? d : d + 4;
    ull h2[2][8];
    #pragma unroll
    for (int s = 0; s < 2; s++)
        #pragma unroll
        for (int q = 0; q < 8; q++) h2[s][q] = 0ull;
    float xm1[2] = {0.f, 0.f}, xm2[2] = {0.f, 0.f}, xm3[2] = {0.f, 0.f};

    for (int tile = 0; tile < SEQ / TT; tile++) {
        const int buf = tile & 1;

        // ---- phase A pass 1: xh -> conv -> silu -> xt_s (wa bank) ----
        {
            ull wa[16];
            #pragma unroll
            for (int qq = 0; qq < 8; qq++) {
                float4 a4 = lds128v(winp_a + (uint32_t)(qq * 128 + d) * 16u);
                wa[2 * qq] = pack2(a4.x, a4.y);
                wa[2 * qq + 1] = pack2(a4.z, a4.w);
            }
            #pragma unroll
            for (int s = 0; s < 2; s++) {
                #pragma unroll 4
                for (int tt = 0; tt < TT; tt++) {
                    ull ax = 0ull;
                    const float4* xp4 = (const float4*)xin_s[buf][team][s][tt];
                    #pragma unroll
                    for (int qq = 0; qq < 8; qq++) {
                        float4 xv4 = xp4[qq];
                        FMA2(ax, wa[2 * qq], pack2(xv4.x, xv4.y), ax);
                        FMA2(ax, wa[2 * qq + 1], pack2(xv4.z, xv4.w), ax);
                    }
                    float2 fx = unpack2(ax);
                    const float xh = fx.x + fx.y;
                    float xc = cb;
                    xc = fmaf(cw.x, xm3[s], xc);
                    xc = fmaf(cw.y, xm2[s], xc);
                    xc = fmaf(cw.z, xm1[s], xc);
                    xc = fmaf(cw.w, xh, xc);
                    xm3[s] = xm2[s]; xm2[s] = xm1[s]; xm1[s] = xh;
                    xt_s[team][s][tt][xpos] = __fdividef(xc, 1.f + __expf(-xc));
                }
            }
        }
        // ---- phase A pass 2: z -> silu -> sz_s (wz bank); input prefetch ----
        {
            const bool ld = (tile + 1 < SEQ / TT);
            float4 pf[2];
            if (ld) {
                #pragma unroll
                for (int r = 0; r < 2; r++) {
                    int f = d + 64 * r;
                    int s = f >> 6, rem = f & 63;
                    pf[r] = *(const float4*)(xbase + s * (SEQ * DM)
                                             + (tile + 1) * (TT * DM) + rem * 4);
                }
            }
            ull wz[16];
            #pragma unroll
            for (int qq = 0; qq < 8; qq++) {
                float4 z4 = lds128v(winp_a + (uint32_t)(qq * 128 + 64 + d) * 16u);
                wz[2 * qq] = pack2(z4.x, z4.y);
                wz[2 * qq + 1] = pack2(z4.z, z4.w);
            }
            #pragma unroll
            for (int s = 0; s < 2; s++) {
                #pragma unroll 4
                for (int tt = 0; tt < TT; tt++) {
                    ull az = 0ull;
                    const float4* xp4 = (const float4*)xin_s[buf][team][s][tt];
                    #pragma unroll
                    for (int qq = 0; qq < 8; qq++) {
                        float4 xv4 = xp4[qq];
                        FMA2(az, wz[2 * qq], pack2(xv4.x, xv4.y), az);
                        FMA2(az, wz[2 * qq + 1], pack2(xv4.z, xv4.w), az);
                    }
                    float2 fz = unpack2(az);
                    const float z = fz.x + fz.y;
                    sz_s[team][s][tt][d] = __fdividef(z, 1.f + __expf(-z));
                }
            }
            if (ld) {
                #pragma unroll
                for (int r = 0; r < 2; r++) {
                    int f = d + 64 * r;
                    int s = f >> 6, rem = f & 63;
                    *(float4*)&xin_s[buf ^ 1][team][s][rem >> 3][(rem & 7) * 4] = pf[r];
                }
            }
        }
        asm volatile("bar.sync %0, 64;" :: "r"(team + 1) : "memory");

        // ---- phase B: x_proj half-rows + dt for both seqs ----
        {
            ull wB[16];
            const int i = 32 * w + l;
            #pragma unroll
            for (int qq = 0; qq < 8; qq++) {
                float4 b4 = lds128v(xpw_a + (uint32_t)(qq * 64 + i) * 16u);
                wB[2 * qq] = pack2(b4.x, b4.y);
                wB[2 * qq + 1] = pack2(b4.z, b4.w);
            }
            const float2 wdv = unpack2(lds64v(wdt_a + (uint32_t)i * 8u));
            const int hbyte = (l & 1) ? 144 : 0;
            const int dtoff = (l < 16) ? 8 * l : 8 * l + 16;
            const int pos = 16 * w + (l >> 1);

            #pragma unroll
            for (int s = 0; s < 2; s++) {
                #pragma unroll 4
                for (int tt = 0; tt < TT; tt++) {
                    const char* rowp = (const char*)&xt_s[team][s][tt][0];
                    const float4* xp = (const float4*)(rowp + hbyte);
                    ull acc = 0ull;
                    #pragma unroll
                    for (int qq = 0; qq < 8; qq++) {
                        float4 xv4 = xp[qq];
                        FMA2(acc, wB[2 * qq], pack2(xv4.x, xv4.y), acc);
                        FMA2(acc, wB[2 * qq + 1], pack2(xv4.z, xv4.w), acc);
                    }
                    float2 a2 = unpack2(acc);
                    float partial = a2.x + a2.y;
                    partial += __shfl_xor_sync(0xffffffffu, partial, 1);
                    if (!(l & 1)) dbc_s[team][s][tt][pos] = partial;

                    float2 xv = *(const float2*)(rowp + dtoff);
                    float u = fmaf(wdv.y, xv.y, wdv.x * xv.x);
                    #pragma unroll
                    for (int off = 16; off; off >>= 1)
                        u += __shfl_xor_sync(0xffffffffu, u, off);
                    if (l == 0) dbc_s[team][s][tt][32 + w] = u;
                }
            }
        }
        asm volatile("bar.sync %0, 64;" :: "r"(team + 1) : "memory");

        // ---- phase C: delta, scan, gate, folded head ----
        #pragma unroll
        for (int s = 0; s < 2; s++) {
            #pragma unroll 4
            for (int tt = 0; tt < TT; tt++) {
                const float* db = dbc_s[team][s][tt];
                const float2 uu = *(const float2*)&db[32];
                const float dpre = fmaf(dtw.x, uu.x, fmaf(dtw.y, uu.y, dtb));
                const float delta = dpre > 15.f ? dpre : __logf(1.f + __expf(dpre));
                const float xt = xt_s[team][s][tt][xpos];
                const float du = delta * xt;
                const ull du2 = pack2(du, du);
                ull y2a = 0ull, y2b = 0ull;
                if (!slow) {
                    const float r = __expf(-delta);
                    const float rr = r * r;
                    ull cur = pack2(r, rr);
                    const ull rrd = pack2(rr, rr);
                    #pragma unroll
                    for (int qq = 0; qq < 4; qq++) {
                        float4 b4 = *(const float4*)&db[4 * qq];
                        float4 c4 = *(const float4*)&db[16 + 4 * qq];
                        ull bp = pack2(b4.x, b4.y), cp = pack2(c4.x, c4.y);
                        ull tmp;
                        MUL2(tmp, bp, du2);
                        FMA2(h2[s][2 * qq], cur, h2[s][2 * qq], tmp);
                        FMA2(y2a, h2[s][2 * qq], cp, y2a);
                        MUL2(cur, cur, rrd);
                        bp = pack2(b4.z, b4.w); cp = pack2(c4.z, c4.w);
                        MUL2(tmp, bp, du2);
                        FMA2(h2[s][2 * qq + 1], cur, h2[s][2 * qq + 1], tmp);
                        FMA2(y2b, h2[s][2 * qq + 1], cp, y2b);
                        if (qq < 3) MUL2(cur, cur, rrd);
                    }
                } else {
                    #pragma unroll
                    for (int qq = 0; qq < 4; qq++) {
                        float4 b4 = *(const float4*)&db[4 * qq];
                        float4 c4 = *(const float4*)&db[16 + 4 * qq];
                        float4 ap = *(const float4*)&a_s[d][4 * qq];
                        ull dA = pack2(__expf(delta * ap.x), __expf(delta * ap.y));
                        ull bp = pack2(b4.x, b4.y), cp = pack2(c4.x, c4.y);
                        ull tmp;
                        MUL2(tmp, bp, du2);
                        FMA2(h2[s][2 * qq], dA, h2[s][2 * qq], tmp);
                        FMA2(y2a, h2[s][2 * qq], cp, y2a);
                        dA = pack2(__expf(delta * ap.z), __expf(delta * ap.w));
                        bp = pack2(b4.z, b4.w); cp = pack2(c4.z, c4.w);
                        MUL2(tmp, bp, du2);
                        FMA2(h2[s][2 * qq + 1], dA, h2[s][2 * qq + 1], tmp);
                        FMA2(y2b, h2[s][2 * qq + 1], cp, y2b);
                    }
                }
                float2 ya = unpack2(y2a), yb = unpack2(y2b);
                float y = (ya.x + ya.y) + (yb.x + yb.y);
                y = fmaf(xt, dpv, y);
                y *= sz_s[team][s][tt][d];

                float acc = y * vv;
                #pragma unroll
                for (int off = 16; off; off >>= 1)
                    acc += __shfl_xor_sync(0xffffffffu, acc, off);
                if (l == 0) part_s[team][s][tile * TT + tt][w] = acc;
            }
        }
        // protect xt_s / sz_s / dbc_s against next tile's writers
        asm volatile("bar.sync %0, 64;" :: "r"(team + 1) : "memory");
    }

    __syncthreads();
    #pragma unroll
    for (int rep = 0; rep < 2; rep++) {
        const int idx = tid + rep * 256;      // 0..511
        const int sj = idx & 7;
        const int t = idx >> 3;
        const float val = part_s[sj >> 1][sj & 1][t][0]
                        + part_s[sj >> 1][sj & 1][t][1] + c_s;
        const int obb = blockIdx.x * 8 + sj;
        out[(obb >> 10) * (SEQ * HW) + t * HW + (obb & (HW - 1))] = val;
    }
}

extern "C" void kernel_launch(void* const* d_in, const int* in_sizes, int n_in,
                              void* d_out, int out_size) {
    const float* x         = (const float*)d_in[0];
    const float* in_proj_w = (const float*)d_in[1];
    const float* conv_w    = (const float*)d_in[2];
    const float* conv_b    = (const float*)d_in[3];
    const float* x_proj_w  = (const float*)d_in[4];
    const float* dt_proj_w = (const float*)d_in[5];
    const float* dt_proj_b = (const float*)d_in[6];
    const float* A_log     = (const float*)d_in[7];
    const float* Dp        = (const float*)d_in[8];
    const float* out_proj_w= (const float*)d_in[9];
    const float* lin1_w    = (const float*)d_in[10];
    const float* lin1_b    = (const float*)d_in[11];
    const float* lin2_w    = (const float*)d_in[12];
    const float* lin2_b    = (const float*)d_in[13];
    float* out = (float*)d_out;

    transpose_kernel<<<2048, 256>>>(x);
    mamba_main<<<256, 256>>>(in_proj_w, conv_w, conv_b, x_proj_w,
                             dt_proj_w, dt_proj_b, A_log, Dp, out_proj_w,
                             lin1_w, lin1_b, lin2_w, lin2_b, out);
}

// round 11
// speedup vs baseline: 1.0284x; 1.0284x over previous
#include <cuda_runtime.h>
#include <cstdint>

typedef unsigned long long ull;

#define SEQ 64
#define DM 32
#define DI 64
#define HW 1024
#define TT 16

#define FMA2(d, a, b, c) \
    asm("fma.rn.f32x2 %0, %1, %2, %3;" : "=l"(d) : "l"(a), "l"(b), "l"(c))
#define MUL2(d, a, b) \
    asm("mul.rn.f32x2 %0, %1, %2;" : "=l"(d) : "l"(a), "l"(b))
__device__ __forceinline__ ull pack2(float lo, float hi) {
    ull r; asm("mov.b64 %0, {%1, %2};" : "=l"(r) : "f"(lo), "f"(hi)); return r;
}
__device__ __forceinline__ float2 unpack2(ull v) {
    float2 f; asm("mov.b64 {%0, %1}, %2;" : "=f"(f.x), "=f"(f.y) : "l"(v)); return f;
}
__device__ __forceinline__ ull lds64v(uint32_t a) {
    ull v; asm volatile("ld.shared.b64 %0, [%1];" : "=l"(v) : "r"(a)); return v;
}
__device__ __forceinline__ float4 lds128v(uint32_t a) {
    float4 v;
    asm volatile("ld.shared.v4.f32 {%0,%1,%2,%3}, [%4];"
                 : "=f"(v.x), "=f"(v.y), "=f"(v.z), "=f"(v.w) : "r"(a));
    return v;
}

__device__ float g_xr[2 * HW * SEQ * DM];

__global__ __launch_bounds__(256) void transpose_kernel(const float* __restrict__ x) {
    __shared__ float tile[DM][65];
    const int bi = blockIdx.x;
    const int c  = bi & 15;
    const int t  = (bi >> 4) & 63;
    const int b  = bi >> 10;
    const float* src = x + ((b * SEQ + t) * DM) * HW + c * 64;
    const int tid = threadIdx.x;
    #pragma unroll
    for (int i = 0; i < 8; i++) {
        int idx = tid + i * 256;
        tile[idx >> 6][idx & 63] = src[(idx >> 6) * HW + (idx & 63)];
    }
    __syncthreads();
    #pragma unroll
    for (int i = 0; i < 8; i++) {
        int idx = tid + i * 256;
        int hw = idx >> 5, m = idx & 31;
        g_xr[(b * HW + c * 64 + hw) * (SEQ * DM) + t * DM + m] = tile[m][hw];
    }
}

// 256 threads = 4 teams x 64; one sequence per team; TT=16 step tiles.
__global__ __launch_bounds__(256, 2) void mamba_main(
    const float* __restrict__ in_proj_w, const float* __restrict__ conv_w,
    const float* __restrict__ conv_b, const float* __restrict__ x_proj_w,
    const float* __restrict__ dt_proj_w, const float* __restrict__ dt_proj_b,
    const float* __restrict__ A_log, const float* __restrict__ Dp,
    const float* __restrict__ out_proj_w, const float* __restrict__ lin1_w,
    const float* __restrict__ lin1_b, const float* __restrict__ lin2_w,
    const float* __restrict__ lin2_b, float* __restrict__ out)
{
    __shared__ float4 winp4[8][128];       // in_proj 4-wide; r<64 xh, r>=64 z
    __shared__ float4 xpw4[8][64];         // B/C half-row 4-wide, i = 32w + l
    __shared__ ull    wdt_u[64];           // dt rows 0/1 pairs
    __shared__ float  xin_s[2][4][TT][DM]; // double-buffered input tiles
    __shared__ float  xt_s[4][TT][64];     // INTERLEAVED: [h0c0|h1c0|h0c1|h1c1|...]
    __shared__ float  sz_s[4][TT][DI];     // silu(z)
    __shared__ float  dbc_s[4][TT][40];    // [0:16)B,[16:32)C,[32]u0,[33]u1
    __shared__ float  part_s[4][SEQ][2];
    __shared__ float  wm_s[DM];
    __shared__ float  v_s[DI];
    __shared__ float  a_s[DI][18];
    __shared__ float  c_s;
    __shared__ int    slow_s;

    const int tid = threadIdx.x;
    const int team = tid >> 6;
    const int d = tid & 63;
    const int w = (tid >> 5) & 1;
    const int l = tid & 31;

    if (tid == 0) slow_s = 0;
    for (int idx = tid; idx < 1024; idx += 256) {
        int qq = idx >> 7, r = idx & 127;
        winp4[qq][r] = *(const float4*)&in_proj_w[r * DM + 4 * qq];
    }
    for (int idx = tid; idx < 512; idx += 256) {
        int qq = idx >> 6, i = idx & 63;
        int wi = i >> 5, li = i & 31;
        int row = 2 + 16 * wi + (li >> 1), half = li & 1;
        xpw4[qq][i] = *(const float4*)&x_proj_w[row * DI + 32 * half + 4 * qq];
    }
    if (tid < 64) {
        int wi = tid >> 5, li = tid & 31;
        float2 p = *(const float2*)&x_proj_w[wi * DI + 2 * li];
        wdt_u[tid] = pack2(p.x, p.y);
    }
    if (tid < DM) {
        float acc = 0.f;
        #pragma unroll
        for (int k = 0; k < 16; k++) acc = fmaf(lin2_w[k], lin1_w[k * 32 + tid], acc);
        wm_s[tid] = acc;
    }
    if (tid == 0) {
        float c = lin2_b[0];
        #pragma unroll
        for (int k = 0; k < 16; k++) c = fmaf(lin2_w[k], lin1_b[k], c);
        c_s = c;
    }
    __syncthreads();
    if (tid < DI) {
        float acc = 0.f;
        #pragma unroll
        for (int m = 0; m < 32; m++) acc = fmaf(wm_s[m], out_proj_w[m * 64 + tid], acc);
        v_s[tid] = acc;
        int bad = 0;
        #pragma unroll
        for (int n = 0; n < 16; n++) {
            float a = -__expf(A_log[tid * 16 + n]);
            a_s[tid][n] = a;
            if (fabsf(a + (float)(n + 1)) > 1e-4f * (float)(n + 1)) bad = 1;
        }
        if (bad) atomicOr(&slow_s, 1);
    }

    const float4 cw = *(const float4*)(conv_w + d * 4);
    const float cb = conv_b[d];
    const float2 dtw = *(const float2*)(dt_proj_w + d * 2);
    const float dtb = dt_proj_b[d];
    const float dpv = Dp[d];

    const int bb = blockIdx.x * 4 + team;
    const float* xbase = g_xr + (size_t)bb * (SEQ * DM);
    // preload tile 0: 16 steps x 32 floats = 128 float4; 2 per thread
    #pragma unroll
    for (int r = 0; r < 2; r++) {
        int f = d + 64 * r;
        float4 v4 = *(const float4*)(xbase + f * 4);
        *(float4*)&xin_s[0][team][f >> 3][(f & 7) * 4] = v4;
    }
    __syncthreads();
    const float vv = v_s[d];
    const int slow = slow_s;

    const uint32_t winp_a = (uint32_t)__cvta_generic_to_shared(&winp4[0][0]);
    const uint32_t xpw_a  = (uint32_t)__cvta_generic_to_shared(&xpw4[0][0]);
    const uint32_t wdt_a  = (uint32_t)__cvta_generic_to_shared(&wdt_u[0]);
    const uint32_t xt_a   = (uint32_t)__cvta_generic_to_shared(&xt_s[team][0][0]);

    // interleaved slot for own channel
    const int xpos = ((d & 31) >> 2) * 8 + ((d & 32) ? 4 : 0) + (d & 3);
    ull h2[8];
    #pragma unroll
    for (int q = 0; q < 8; q++) h2[q] = 0ull;
    float xm1 = 0.f, xm2 = 0.f, xm3 = 0.f;

    for (int tile = 0; tile < SEQ / TT; tile++) {
        const int buf = tile & 1;

        // ---- phase A: in_proj (both banks) + conv + silu -> xt_s, sz_s ----
        {
            ull wa[16], wz[16];
            #pragma unroll
            for (int qq = 0; qq < 8; qq++) {
                float4 a4 = lds128v(winp_a + (uint32_t)(qq * 128 + d) * 16u);
                wa[2 * qq] = pack2(a4.x, a4.y);
                wa[2 * qq + 1] = pack2(a4.z, a4.w);
                float4 z4 = lds128v(winp_a + (uint32_t)(qq * 128 + 64 + d) * 16u);
                wz[2 * qq] = pack2(z4.x, z4.y);
                wz[2 * qq + 1] = pack2(z4.z, z4.w);
            }
            #pragma unroll 4
            for (int tt = 0; tt < TT; tt++) {
                ull ax = 0ull, az = 0ull;
                const float4* xp4 = (const float4*)xin_s[buf][team][tt];
                #pragma unroll
                for (int qq = 0; qq < 8; qq++) {
                    float4 xv4 = xp4[qq];
                    ull lo = pack2(xv4.x, xv4.y);
                    ull hi = pack2(xv4.z, xv4.w);
                    FMA2(ax, wa[2 * qq], lo, ax);
                    FMA2(az, wz[2 * qq], lo, az);
                    FMA2(ax, wa[2 * qq + 1], hi, ax);
                    FMA2(az, wz[2 * qq + 1], hi, az);
                }
                float2 fx = unpack2(ax), fz = unpack2(az);
                const float xh = fx.x + fx.y;
                const float z = fz.x + fz.y;
                float xc = cb;
                xc = fmaf(cw.x, xm3, xc);
                xc = fmaf(cw.y, xm2, xc);
                xc = fmaf(cw.z, xm1, xc);
                xc = fmaf(cw.w, xh, xc);
                xm3 = xm2; xm2 = xm1; xm1 = xh;
                xt_s[team][tt][xpos] = __fdividef(xc, 1.f + __expf(-xc));
                sz_s[team][tt][d] = __fdividef(z, 1.f + __expf(-z));
            }
        }
        asm volatile("bar.sync %0, 64;" :: "r"(team + 1) : "memory");

        // ---- phase B: x_proj half-rows + dt; input prefetch ----
        {
            const bool ld = (tile + 1 < SEQ / TT);
            float4 pf[2];
            if (ld) {
                #pragma unroll
                for (int r = 0; r < 2; r++) {
                    int f = d + 64 * r;
                    pf[r] = *(const float4*)(xbase + (tile + 1) * (TT * DM) + f * 4);
                }
            }
            ull wB[16];
            const int i = 32 * w + l;
            #pragma unroll
            for (int qq = 0; qq < 8; qq++) {
                float4 b4 = lds128v(xpw_a + (uint32_t)(qq * 64 + i) * 16u);
                wB[2 * qq] = pack2(b4.x, b4.y);
                wB[2 * qq + 1] = pack2(b4.z, b4.w);
            }
            const float2 wdv = unpack2(lds64v(wdt_a + (uint32_t)i * 8u));
            const uint32_t hoff = (uint32_t)(l & 1) * 16u;   // half within 32B pair
            // dt: own-channel float2 in interleaved layout
            const int d0 = 2 * l;
            const int dtf = (d0 < 32) ? ((d0 >> 2) * 8 + (d0 & 3))
                                      : (((d0 - 32) >> 2) * 8 + 4 + (d0 & 3));
            const int pos = 16 * w + (l >> 1);

            #pragma unroll 4
            for (int tt = 0; tt < TT; tt++) {
                const uint32_t rowa = xt_a + (uint32_t)tt * 256u;
                ull acc = 0ull;
                #pragma unroll
                for (int qq = 0; qq < 8; qq++) {
                    float4 xv4 = lds128v(rowa + (uint32_t)qq * 32u + hoff);
                    FMA2(acc, wB[2 * qq], pack2(xv4.x, xv4.y), acc);
                    FMA2(acc, wB[2 * qq + 1], pack2(xv4.z, xv4.w), acc);
                }
                float2 a2 = unpack2(acc);
                float partial = a2.x + a2.y;
                partial += __shfl_xor_sync(0xffffffffu, partial, 1);
                if (!(l & 1)) dbc_s[team][tt][pos] = partial;

                float2 xv = unpack2(lds64v(rowa + (uint32_t)dtf * 4u));
                float u = fmaf(wdv.y, xv.y, wdv.x * xv.x);
                #pragma unroll
                for (int off = 16; off; off >>= 1)
                    u += __shfl_xor_sync(0xffffffffu, u, off);
                if (l == 0) dbc_s[team][tt][32 + w] = u;
            }
            if (ld) {
                #pragma unroll
                for (int r = 0; r < 2; r++) {
                    int f = d + 64 * r;
                    *(float4*)&xin_s[buf ^ 1][team][f >> 3][(f & 7) * 4] = pf[r];
                }
            }
        }
        asm volatile("bar.sync %0, 64;" :: "r"(team + 1) : "memory");

        // ---- phase C: delta, scan, gate, folded head ----
        #pragma unroll 4
        for (int tt = 0; tt < TT; tt++) {
            const float* db = dbc_s[team][tt];
            const float2 uu = *(const float2*)&db[32];
            const float dpre = fmaf(dtw.x, uu.x, fmaf(dtw.y, uu.y, dtb));
            const float delta = dpre > 15.f ? dpre : __logf(1.f + __expf(dpre));
            const float xt = xt_s[team][tt][xpos];
            const float du = delta * xt;
            const ull du2 = pack2(du, du);
            ull y2a = 0ull, y2b = 0ull;
            if (!slow) {
                const float r = __expf(-delta);
                const float rr = r * r;
                ull cur = pack2(r, rr);
                const ull rrd = pack2(rr, rr);
                #pragma unroll
                for (int qq = 0; qq < 4; qq++) {
                    float4 b4 = *(const float4*)&db[4 * qq];
                    float4 c4 = *(const float4*)&db[16 + 4 * qq];
                    ull bp = pack2(b4.x, b4.y), cp = pack2(c4.x, c4.y);
                    ull tmp;
                    MUL2(tmp, bp, du2);
                    FMA2(h2[2 * qq], cur, h2[2 * qq], tmp);
                    FMA2(y2a, h2[2 * qq], cp, y2a);
                    MUL2(cur, cur, rrd);
                    bp = pack2(b4.z, b4.w); cp = pack2(c4.z, c4.w);
                    MUL2(tmp, bp, du2);
                    FMA2(h2[2 * qq + 1], cur, h2[2 * qq + 1], tmp);
                    FMA2(y2b, h2[2 * qq + 1], cp, y2b);
                    if (qq < 3) MUL2(cur, cur, rrd);
                }
            } else {
                #pragma unroll
                for (int qq = 0; qq < 4; qq++) {
                    float4 b4 = *(const float4*)&db[4 * qq];
                    float4 c4 = *(const float4*)&db[16 + 4 * qq];
                    float4 ap = *(const float4*)&a_s[d][4 * qq];
                    ull dA = pack2(__expf(delta * ap.x), __expf(delta * ap.y));
                    ull bp = pack2(b4.x, b4.y), cp = pack2(c4.x, c4.y);
                    ull tmp;
                    MUL2(tmp, bp, du2);
                    FMA2(h2[2 * qq], dA, h2[2 * qq], tmp);
                    FMA2(y2a, h2[2 * qq], cp, y2a);
                    dA = pack2(__expf(delta * ap.z), __expf(delta * ap.w));
                    bp = pack2(b4.z, b4.w); cp = pack2(c4.z, c4.w);
                    MUL2(tmp, bp, du2);
                    FMA2(h2[2 * qq + 1], dA, h2[2 * qq + 1], tmp);
                    FMA2(y2b, h2[2 * qq + 1], cp, y2b);
                }
            }
            float2 ya = unpack2(y2a), yb = unpack2(y2b);
            float y = (ya.x + ya.y) + (yb.x + yb.y);
            y = fmaf(xt, dpv, y);
            y *= sz_s[team][tt][d];

            float acc = y * vv;
            #pragma unroll
            for (int off = 16; off; off >>= 1)
                acc += __shfl_xor_sync(0xffffffffu, acc, off);
            if (l == 0) part_s[team][tile * TT + tt][w] = acc;
        }
        // no third barrier needed: C reads only self-written xt/sz slots,
        // and cross-warp dbc reuse is fenced by next tile's bar1 via program order
    }

    __syncthreads();
    {
        const int tt = tid >> 2;
        const int jj = tid & 3;
        const float val = part_s[jj][tt][0] + part_s[jj][tt][1] + c_s;
        const int obb = blockIdx.x * 4 + jj;
        out[(obb >> 10) * (SEQ * HW) + tt * HW + (obb & (HW - 1))] = val;
    }
}

extern "C" void kernel_launch(void* const* d_in, const int* in_sizes, int n_in,
                              void* d_out, int out_size) {
    const float* x         = (const float*)d_in[0];
    const float* in_proj_w = (const float*)d_in[1];
    const float* conv_w    = (const float*)d_in[2];
    const float* conv_b    = (const float*)d_in[3];
    const float* x_proj_w  = (const float*)d_in[4];
    const float* dt_proj_w = (const float*)d_in[5];
    const float* dt_proj_b = (const float*)d_in[6];
    const float* A_log     = (const float*)d_in[7];
    const float* Dp        = (const float*)d_in[8];
    const float* out_proj_w= (const float*)d_in[9];
    const float* lin1_w    = (const float*)d_in[10];
    const float* lin1_b    = (const float*)d_in[11];
    const float* lin2_w    = (const float*)d_in[12];
    const float* lin2_b    = (const float*)d_in[13];
    float* out = (float*)d_out;

    transpose_kernel<<<2048, 256>>>(x);
    mamba_main<<<512, 256>>>(in_proj_w, conv_w, conv_b, x_proj_w,
                             dt_proj_w, dt_proj_b, A_log, Dp, out_proj_w,
                             lin1_w, lin1_b, lin2_w, lin2_b, out);
}